// round 16
// baseline (speedup 1.0000x reference)
#include <cuda_runtime.h>
#include <math.h>

#define N_NODES 131072
#define N_EDGES 1048576
#define F_DIM   32
#define H_DIM   128
#define G_NUM   512
#define SLOTS   40

// Output layout (float32, concatenated in reference return order)
#define OUT_A   0LL         // [512,5]
#define OUT_S   2560LL      // [512,1000]
#define OUT_T   514560LL    // [512,1000]
#define OUT_ACT 1026560LL   // [512,4]
#define OUT_V   1028608LL   // [512,1]

// ---------------- scratch (static device globals; no allocation) ----------
__device__ float d_msgF[N_NODES * F_DIM];  // 16 MB : msgF = segment_sum(w*nf[src])
__device__ float d_B[2 * F_DIM * H_DIM];   // 32 KB : [[Win],[Win@Wmsg]]
__device__ float d_gsum[G_NUM * H_DIM];
__device__ float d_s2[G_NUM * 64];
__device__ int   d_flag64;
__device__ int   d_cnt[N_NODES];
__device__ unsigned long long d_eslot[(size_t)N_NODES * SLOTS];  // 42 MB: per-node slot rows

// ---------------- helpers -------------------------------------------------
__device__ __forceinline__ long long ldidx(const void* p, long long i, int f64) {
    if (f64) return ((const long long*)p)[i];
    return (long long)((const int*)p)[i];
}

__device__ __forceinline__ void red_add_v4(float* ptr, float a, float b, float c, float d) {
    asm volatile("red.global.add.v4.f32 [%0], {%1,%2,%3,%4};"
                 :: "l"(ptr), "f"(a), "f"(b), "f"(c), "f"(d) : "memory");
}

// packed fp32x2 (Blackwell sm_100+): 2 FMAs per issue slot
__device__ __forceinline__ unsigned long long pk2(float lo, float hi) {
    unsigned long long r;
    asm("mov.b64 %0, {%1, %2};" : "=l"(r) : "f"(lo), "f"(hi));
    return r;
}
__device__ __forceinline__ void upk2(float& lo, float& hi, unsigned long long v) {
    asm("mov.b64 {%0, %1}, %2;" : "=f"(lo), "=f"(hi) : "l"(v));
}
__device__ __forceinline__ void fma2(unsigned long long& d, unsigned long long a, unsigned long long b) {
    asm("fma.rn.f32x2 %0, %1, %2, %0;" : "+l"(d) : "l"(a), "l"(b));
}

// ---------------- kernel 0: setup (detect + build B + zero cnt/gsum) ------
__global__ void k_setup(const void* __restrict__ eidx,
                        const float* __restrict__ Win, const float* __restrict__ Wmsg) {
    int b = blockIdx.x, t = threadIdx.x;
    int i = b * 256 + t;
    d_cnt[i] = 0;
    if (i < G_NUM * H_DIM) d_gsum[i] = 0.f;

    __shared__ float wrow[H_DIM];
    if (b >= 32 && b < 64) {                    // C rows: C = Win @ Wmsg
        int k = b - 32;
        if (t < 128) wrow[t] = Win[k * H_DIM + t];
        __syncthreads();
        if (t < 128) {
            float acc = 0.f;
            #pragma unroll 4
            for (int m = 0; m < H_DIM; m++) acc += wrow[m] * __ldg(Wmsg + m * H_DIM + t);
            d_B[(32 + k) * H_DIM + t] = acc;
        }
    } else if (b < 32) {                        // Win rows copied
        if (t < 128) d_B[b * H_DIM + t] = Win[b * H_DIM + t];
    }
    if (b == 0) {                               // parallel int64-vs-int32 detect
        int nz = 0;
        if (t < 128) nz = (((const unsigned*)eidx)[2 * t + 1] != 0u);
        int any = __syncthreads_or(nz);
        if (t == 0) d_flag64 = any ? 0 : 1;
    }
}

// ---------------- kernel 1: slotted scatter (counting + placement) --------
__global__ void k_scatter(const void* __restrict__ eidx, const float* __restrict__ ew) {
    const int f64 = d_flag64;
    int base = blockIdx.x * 512 + threadIdx.x;
    #pragma unroll
    for (int q = 0; q < 2; q++) {
        int e = base + q * 256;
        long long src = ldidx(eidx, e, f64);
        long long tgt = ldidx(eidx, (long long)N_EDGES + e, f64);
        float w = __ldg(ew + e);
        int pos = atomicAdd(&d_cnt[tgt], 1);
        if (pos < SLOTS)
            d_eslot[(size_t)tgt * SLOTS + pos] =
                ((unsigned long long)__float_as_uint(w) << 32) | (unsigned)(int)src;
    }
}

// ---------------- kernel 2: F-space gather: msgF[n] = sum w*nf[src] -------
__global__ void k_gatherF(const float* __restrict__ nf) {
    int sub = threadIdx.x >> 3;
    int l = threadIdx.x & 7;
    int n = blockIdx.x * 32 + sub;
    int cnt = d_cnt[n];
    if (cnt > SLOTS) cnt = SLOTS;
    const unsigned long long* ep = d_eslot + (size_t)n * SLOTS;

    float4 a0 = {0.f, 0.f, 0.f, 0.f};
    float4 a1 = {0.f, 0.f, 0.f, 0.f};
    float4 a2 = {0.f, 0.f, 0.f, 0.f};
    float4 a3 = {0.f, 0.f, 0.f, 0.f};
    int i = 0;
    for (; i + 3 < cnt; i += 4) {
        unsigned long long p0 = ep[i];
        unsigned long long p1 = ep[i + 1];
        unsigned long long p2 = ep[i + 2];
        unsigned long long p3 = ep[i + 3];
        int s0 = (int)(unsigned)p0; float w0 = __uint_as_float((unsigned)(p0 >> 32));
        int s1 = (int)(unsigned)p1; float w1 = __uint_as_float((unsigned)(p1 >> 32));
        int s2 = (int)(unsigned)p2; float w2 = __uint_as_float((unsigned)(p2 >> 32));
        int s3 = (int)(unsigned)p3; float w3 = __uint_as_float((unsigned)(p3 >> 32));
        float4 v0 = *(const float4*)(nf + (size_t)s0 * F_DIM + l * 4);
        float4 v1 = *(const float4*)(nf + (size_t)s1 * F_DIM + l * 4);
        float4 v2 = *(const float4*)(nf + (size_t)s2 * F_DIM + l * 4);
        float4 v3 = *(const float4*)(nf + (size_t)s3 * F_DIM + l * 4);
        a0.x += v0.x * w0; a0.y += v0.y * w0; a0.z += v0.z * w0; a0.w += v0.w * w0;
        a1.x += v1.x * w1; a1.y += v1.y * w1; a1.z += v1.z * w1; a1.w += v1.w * w1;
        a2.x += v2.x * w2; a2.y += v2.y * w2; a2.z += v2.z * w2; a2.w += v2.w * w2;
        a3.x += v3.x * w3; a3.y += v3.y * w3; a3.z += v3.z * w3; a3.w += v3.w * w3;
    }
    for (; i < cnt; i++) {
        unsigned long long p0 = ep[i];
        int s0 = (int)(unsigned)p0; float w0 = __uint_as_float((unsigned)(p0 >> 32));
        float4 v0 = *(const float4*)(nf + (size_t)s0 * F_DIM + l * 4);
        a0.x += v0.x * w0; a0.y += v0.y * w0; a0.z += v0.z * w0; a0.w += v0.w * w0;
    }
    a0.x += a1.x + a2.x + a3.x;
    a0.y += a1.y + a2.y + a3.y;
    a0.z += a1.z + a2.z + a3.z;
    a0.w += a1.w + a2.w + a3.w;
    *(float4*)(d_msgF + (size_t)n * F_DIM + l * 4) = a0;
}

// ---------------- kernel 3: h = relu([nf,msgF]@B); pool into gsum ---------
// 128x128 block tile, 256 threads, 8x8 micro-tile, f32x2 FMA (R10-proven).
__global__ __launch_bounds__(256, 2) void k_gemm_pool(const float* __restrict__ nf,
                                                      const void* __restrict__ batch) {
    __shared__ float As[16][132];   // [k][row]; stride 132 = 0 mod 4 -> float4-aligned rows
    __shared__ float Bs[16][132];   // [k][col]
    const int f64 = d_flag64;
    int t = threadIdx.x;
    int rowBase = blockIdx.x * 128;
    int tc = t & 15, tr = t >> 4;   // 16x16 thread grid: 8 cols x 8 rows each

    unsigned long long acc[8][4];   // [row][col-pair] f32x2
    #pragma unroll
    for (int i = 0; i < 8; i++)
        #pragma unroll
        for (int j = 0; j < 4; j++) acc[i][j] = 0ULL;

    int ar_row = t >> 1, ar_half = t & 1;       // A loader mapping
    int bk = t >> 4, bc = (t & 15) * 8;         // B loader mapping

    #pragma unroll
    for (int p = 0; p < 2; p++) {
        const float* Asrc = p ? d_msgF : nf;
        #pragma unroll
        for (int c = 0; c < 2; c++) {
            // A chunk: 128 rows x 16 k (transposed): thread loads 8 floats
            {
                const float4* ar = (const float4*)(Asrc + (size_t)(rowBase + ar_row) * F_DIM
                                                   + c * 16 + ar_half * 8);
                float4 v0 = ar[0], v1 = ar[1];
                int kb = ar_half * 8;
                As[kb + 0][ar_row] = v0.x; As[kb + 1][ar_row] = v0.y;
                As[kb + 2][ar_row] = v0.z; As[kb + 3][ar_row] = v0.w;
                As[kb + 4][ar_row] = v1.x; As[kb + 5][ar_row] = v1.y;
                As[kb + 6][ar_row] = v1.z; As[kb + 7][ar_row] = v1.w;
            }
            // B chunk: 16 k x 128 cols: thread loads 8 floats
            {
                const float4* wr = (const float4*)(d_B + (size_t)(p * 32 + c * 16 + bk) * H_DIM + bc);
                *(float4*)&Bs[bk][bc]     = wr[0];
                *(float4*)&Bs[bk][bc + 4] = wr[1];
            }
            __syncthreads();

            #pragma unroll
            for (int kk = 0; kk < 16; kk++) {
                float4 a0 = *(const float4*)&As[kk][tr * 8];
                float4 a1 = *(const float4*)&As[kk][tr * 8 + 4];
                float4 b0 = *(const float4*)&Bs[kk][tc * 8];
                float4 b1 = *(const float4*)&Bs[kk][tc * 8 + 4];
                unsigned long long bp0 = pk2(b0.x, b0.y);
                unsigned long long bp1 = pk2(b0.z, b0.w);
                unsigned long long bp2 = pk2(b1.x, b1.y);
                unsigned long long bp3 = pk2(b1.z, b1.w);
                float av[8] = {a0.x, a0.y, a0.z, a0.w, a1.x, a1.y, a1.z, a1.w};
                #pragma unroll
                for (int i = 0; i < 8; i++) {
                    unsigned long long ap = pk2(av[i], av[i]);
                    fma2(acc[i][0], ap, bp0);
                    fma2(acc[i][1], ap, bp1);
                    fma2(acc[i][2], ap, bp2);
                    fma2(acc[i][3], ap, bp3);
                }
            }
            __syncthreads();
        }
    }

    // epilogue: relu + pool into per-graph sums
    int c0 = tc * 8;
    int r0 = rowBase + tr * 8;
    long long gidA = ldidx(batch, r0, f64);
    long long gidB = ldidx(batch, r0 + 7, f64);

    if (gidA == gidB) {   // sorted batch => all 8 rows same graph
        float s[8];
        #pragma unroll
        for (int j = 0; j < 8; j++) s[j] = 0.f;
        #pragma unroll
        for (int i = 0; i < 8; i++)
            #pragma unroll
            for (int j4 = 0; j4 < 4; j4++) {
                float lo, hi;
                upk2(lo, hi, acc[i][j4]);
                s[2 * j4]     += fmaxf(lo, 0.f);
                s[2 * j4 + 1] += fmaxf(hi, 0.f);
            }
        float* base = d_gsum + gidA * H_DIM + c0;
        red_add_v4(base,     s[0], s[1], s[2], s[3]);
        red_add_v4(base + 4, s[4], s[5], s[6], s[7]);
    } else {
        #pragma unroll
        for (int i = 0; i < 8; i++) {
            long long gid = ldidx(batch, r0 + i, f64);
            float v[8];
            #pragma unroll
            for (int j4 = 0; j4 < 4; j4++) {
                float lo, hi;
                upk2(lo, hi, acc[i][j4]);
                v[2 * j4]     = fmaxf(lo, 0.f);
                v[2 * j4 + 1] = fmaxf(hi, 0.f);
            }
            float* base = d_gsum + gid * H_DIM + c0;
            red_add_v4(base,     v[0], v[1], v[2], v[3]);
            red_add_v4(base + 4, v[4], v[5], v[6], v[7]);
        }
    }
}

// ---------------- kernel 4a: backbone + small heads, 8 graphs per block ---
__global__ void k_head_small8(const void* __restrict__ batch,
                              const float* __restrict__ W1, const float* __restrict__ W2,
                              const float* __restrict__ Wa, const float* __restrict__ Wact,
                              const float* __restrict__ Wv1, const float* __restrict__ Wv2,
                              float* __restrict__ out) {
    __shared__ float sg[8][128];
    __shared__ float s1s[8][128];
    __shared__ float ss[8][64];
    __shared__ float v1s[8][32];
    __shared__ float inv8[8];
    const int f64 = d_flag64;
    int gbase = blockIdx.x * 8, t = threadIdx.x;

    if (t < 8) {
        long long g = gbase + t;
        int lo = 0, hi = N_NODES;
        while (lo < hi) { int mid = (lo + hi) >> 1; if (ldidx(batch, mid, f64) < g) lo = mid + 1; else hi = mid; }
        int start = lo;
        hi = N_NODES;
        while (lo < hi) { int mid = (lo + hi) >> 1; if (ldidx(batch, mid, f64) < g + 1) lo = mid + 1; else hi = mid; }
        int cnt = lo - start;
        inv8[t] = (cnt > 0) ? 1.f / (float)cnt : 0.f;
    }
    __syncthreads();

    #pragma unroll
    for (int g8 = 0; g8 < 8; g8++)
        sg[g8][t] = d_gsum[(size_t)(gbase + g8) * H_DIM + t] * inv8[g8];
    __syncthreads();

    {
        float acc[8];
        #pragma unroll
        for (int g8 = 0; g8 < 8; g8++) acc[g8] = 0.f;
        #pragma unroll 4
        for (int k = 0; k < 128; k++) {
            float wv = __ldg(W1 + k * 128 + t) + __ldg(W1 + (k + 128) * 128 + t);
            #pragma unroll
            for (int g8 = 0; g8 < 8; g8++) acc[g8] += sg[g8][k] * wv;
        }
        #pragma unroll
        for (int g8 = 0; g8 < 8; g8++) s1s[g8][t] = fmaxf(acc[g8], 0.f);
    }
    __syncthreads();

    if (t < 64) {
        float acc[8];
        #pragma unroll
        for (int g8 = 0; g8 < 8; g8++) acc[g8] = 0.f;
        #pragma unroll 4
        for (int k = 0; k < 128; k++) {
            float wv = __ldg(W2 + k * 64 + t);
            #pragma unroll
            for (int g8 = 0; g8 < 8; g8++) acc[g8] += s1s[g8][k] * wv;
        }
        #pragma unroll
        for (int g8 = 0; g8 < 8; g8++) {
            float v = fmaxf(acc[g8], 0.f);
            ss[g8][t] = v;
            d_s2[(size_t)(gbase + g8) * 64 + t] = v;
        }
    }
    __syncthreads();

    if (t < 40) {
        int g8 = t / 5, j = t - g8 * 5;
        float acc = 0.f;
        #pragma unroll
        for (int k = 0; k < 64; k++) acc += ss[g8][k] * __ldg(Wa + k * 5 + j);
        out[OUT_A + (long long)(gbase + g8) * 5 + j] = acc;
    }
    if (t >= 64 && t < 96) {
        int idx = t - 64, g8 = idx >> 2, j = idx & 3;
        float acc = 0.f;
        #pragma unroll
        for (int k = 0; k < 64; k++) acc += ss[g8][k] * __ldg(Wact + k * 4 + j);
        out[OUT_ACT + (long long)(gbase + g8) * 4 + j] = acc;
    }
    {
        int g8 = t >> 4, jb = t & 15;
        #pragma unroll
        for (int rep = 0; rep < 2; rep++) {
            int j = jb + rep * 16;
            float acc = 0.f;
            #pragma unroll
            for (int k = 0; k < 64; k++) acc += ss[g8][k] * __ldg(Wv1 + k * 32 + j);
            v1s[g8][j] = fmaxf(acc, 0.f);
        }
    }
    __syncthreads();
    if (t < 8) {
        float acc = 0.f;
        #pragma unroll
        for (int k = 0; k < 32; k++) acc += v1s[t][k] * __ldg(Wv2 + k);
        out[OUT_V + gbase + t] = tanhf(acc);
    }
}

// ---------------- kernel 4b: big heads (source/target logits) -------------
__global__ void k_head_big(const float* __restrict__ Ws, const float* __restrict__ Wt,
                           float* __restrict__ out) {
    __shared__ float s2s[8][64];
    int gbase = blockIdx.x * 8;
    const float* W = blockIdx.y ? Wt : Ws;
    long long off = blockIdx.y ? OUT_T : OUT_S;
    int t = threadIdx.x;

    for (int i = t; i < 512; i += 128) s2s[i >> 6][i & 63] = d_s2[gbase * 64 + i];
    __syncthreads();

    for (int m = t; m < 1000; m += 128) {
        float acc[8];
        #pragma unroll
        for (int g8 = 0; g8 < 8; g8++) acc[g8] = 0.f;
        #pragma unroll 8
        for (int k = 0; k < 64; k++) {
            float wv = __ldg(W + k * 1000 + m);
            #pragma unroll
            for (int g8 = 0; g8 < 8; g8++) acc[g8] += s2s[g8][k] * wv;
        }
        #pragma unroll
        for (int g8 = 0; g8 < 8; g8++)
            out[off + (long long)(gbase + g8) * 1000 + m] = acc[g8];
    }
}

// ---------------- launch ---------------------------------------------------
extern "C" void kernel_launch(void* const* d_in, const int* in_sizes, int n_in,
                              void* d_out, int out_size) {
    const float* nf   = (const float*)d_in[0];
    const void*  eidx = d_in[1];
    const float* ew   = (const float*)d_in[2];
    // d_in[3] = layer_positions (unused)
    const void*  batch = d_in[4];
    int wb = n_in - 10;
    const float* Win  = (const float*)d_in[wb + 0];
    const float* Wmsg = (const float*)d_in[wb + 1];
    const float* W1   = (const float*)d_in[wb + 2];
    const float* W2   = (const float*)d_in[wb + 3];
    const float* Wa   = (const float*)d_in[wb + 4];
    const float* Ws   = (const float*)d_in[wb + 5];
    const float* Wt   = (const float*)d_in[wb + 6];
    const float* Wact = (const float*)d_in[wb + 7];
    const float* Wv1  = (const float*)d_in[wb + 8];
    const float* Wv2  = (const float*)d_in[wb + 9];
    float* out = (float*)d_out;

    k_setup<<<N_NODES / 256, 256>>>(eidx, Win, Wmsg);
    k_scatter<<<N_EDGES / 512, 256>>>(eidx, ew);
    k_gatherF<<<N_NODES / 32, 256>>>(nf);
    k_gemm_pool<<<N_NODES / 128, 256>>>(nf, batch);
    k_head_small8<<<G_NUM / 8, 128>>>(batch, W1, W2, Wa, Wact, Wv1, Wv2, out);
    k_head_big<<<dim3(64, 2), 128>>>(Ws, Wt, out);
}

// round 17
// speedup vs baseline: 1.1931x; 1.1931x over previous
#include <cuda_runtime.h>
#include <math.h>

#define N_NODES 131072
#define N_EDGES 1048576
#define F_DIM   32
#define H_DIM   128
#define G_NUM   512

// Output layout (float32, concatenated in reference return order)
#define OUT_A   0LL         // [512,5]
#define OUT_S   2560LL      // [512,1000]
#define OUT_T   514560LL    // [512,1000]
#define OUT_ACT 1026560LL   // [512,4]
#define OUT_V   1028608LL   // [512,1]

// ---------------- scratch (static device globals; no allocation) ----------
__device__ float d_msgF[N_NODES * F_DIM];  // 16 MB : msgF = segment_sum(w*nf[src])
__device__ float d_B[2 * F_DIM * H_DIM];   // 32 KB : [[Win],[Win@Wmsg]]
__device__ float d_gsum[G_NUM * H_DIM];
__device__ float d_s2[G_NUM * 64];
__device__ int   d_flag64;
__device__ int   d_cnt[N_NODES];
__device__ int   d_off[N_NODES + 1];
__device__ int   d_cur[N_NODES];
__device__ int   d_bsum[512];
__device__ int   d_bbase[512];
__device__ unsigned long long d_epack[N_EDGES];   // 8 MB: (w_bits<<32)|src

// ---------------- helpers -------------------------------------------------
__device__ __forceinline__ long long ldidx(const void* p, long long i, int f64) {
    if (f64) return ((const long long*)p)[i];
    return (long long)((const int*)p)[i];
}

__device__ __forceinline__ void red_add_v4(float* ptr, float a, float b, float c, float d) {
    asm volatile("red.global.add.v4.f32 [%0], {%1,%2,%3,%4};"
                 :: "l"(ptr), "f"(a), "f"(b), "f"(c), "f"(d) : "memory");
}

// packed fp32x2 (Blackwell sm_100+): 2 FMAs per issue slot
__device__ __forceinline__ unsigned long long pk2(float lo, float hi) {
    unsigned long long r;
    asm("mov.b64 %0, {%1, %2};" : "=l"(r) : "f"(lo), "f"(hi));
    return r;
}
__device__ __forceinline__ void upk2(float& lo, float& hi, unsigned long long v) {
    asm("mov.b64 {%0, %1}, %2;" : "=f"(lo), "=f"(hi) : "l"(v));
}
__device__ __forceinline__ void fma2(unsigned long long& d, unsigned long long a, unsigned long long b) {
    asm("fma.rn.f32x2 %0, %1, %2, %0;" : "+l"(d) : "l"(a), "l"(b));
}

// ---------------- kernel 0: setup (detect + build B + zero scratch) -------
__global__ void k_setup(const void* __restrict__ eidx,
                        const float* __restrict__ Win, const float* __restrict__ Wmsg) {
    int b = blockIdx.x, t = threadIdx.x;
    int i = b * 256 + t;
    d_cnt[i] = 0;
    if (i < G_NUM * H_DIM) d_gsum[i] = 0.f;
    if (i == 0) d_off[N_NODES] = N_EDGES;

    __shared__ float wrow[H_DIM];
    if (b >= 32 && b < 64) {                    // C rows: C = Win @ Wmsg
        int k = b - 32;
        if (t < 128) wrow[t] = Win[k * H_DIM + t];
        __syncthreads();
        if (t < 128) {
            float acc = 0.f;
            #pragma unroll 4
            for (int m = 0; m < H_DIM; m++) acc += wrow[m] * __ldg(Wmsg + m * H_DIM + t);
            d_B[(32 + k) * H_DIM + t] = acc;
        }
    } else if (b < 32) {                        // Win rows copied
        if (t < 128) d_B[b * H_DIM + t] = Win[b * H_DIM + t];
    }
    if (b == 0) {                               // parallel int64-vs-int32 detect
        int nz = 0;
        if (t < 128) nz = (((const unsigned*)eidx)[2 * t + 1] != 0u);
        int any = __syncthreads_or(nz);
        if (t == 0) d_flag64 = any ? 0 : 1;
    }
}

// ---------------- kernel 2a: degree histogram (4 edges/thread) ------------
__global__ void k_hist(const void* __restrict__ eidx) {
    const int f64 = d_flag64;
    int base = blockIdx.x * 1024 + threadIdx.x;
    #pragma unroll
    for (int q = 0; q < 4; q++) {
        long long tgt = ldidx(eidx, (long long)N_EDGES + base + q * 256, f64);
        atomicAdd(&d_cnt[tgt], 1);
    }
}

// ---------------- kernel 2b: hierarchical exclusive scan (3 stages) -------
__global__ void k_scan1() {
    __shared__ int wsum[8];
    int t = threadIdx.x;
    int i = blockIdx.x * 256 + t;
    int lane = t & 31, wid = t >> 5;
    int c = d_cnt[i];
    int v = c;
    #pragma unroll
    for (int off = 1; off < 32; off <<= 1) {
        int u = __shfl_up_sync(0xffffffffu, v, off);
        if (lane >= off) v += u;
    }
    if (lane == 31) wsum[wid] = v;
    __syncthreads();
    if (t < 8) {
        int w = wsum[t];
        #pragma unroll
        for (int off = 1; off < 8; off <<= 1) {
            int u = __shfl_up_sync(0xffu, w, off);
            if (t >= off) w += u;
        }
        wsum[t] = w;
    }
    __syncthreads();
    int warpBase = (wid == 0) ? 0 : wsum[wid - 1];
    d_off[i] = warpBase + v - c;          // local exclusive (no block base yet)
    if (t == 255) d_bsum[blockIdx.x] = wsum[7];
}

__global__ void k_scan2() {
    __shared__ int s[512];
    int t = threadIdx.x;
    s[t] = d_bsum[t];
    __syncthreads();
    #pragma unroll
    for (int off = 1; off < 512; off <<= 1) {
        int v = (t >= off) ? s[t - off] : 0;
        __syncthreads();
        s[t] += v;
        __syncthreads();
    }
    d_bbase[t] = (t == 0) ? 0 : s[t - 1];
}

__global__ void k_scan3() {
    int i = blockIdx.x * 256 + threadIdx.x;
    int v = d_off[i] + d_bbase[blockIdx.x];
    d_off[i] = v;
    d_cur[i] = v;
}

// ---------------- kernel 2c: scatter edges into CSR order (2/thread) ------
__global__ void k_scatter(const void* __restrict__ eidx, const float* __restrict__ ew) {
    const int f64 = d_flag64;
    int base = blockIdx.x * 512 + threadIdx.x;
    #pragma unroll
    for (int q = 0; q < 2; q++) {
        int e = base + q * 256;
        long long src = ldidx(eidx, e, f64);
        long long tgt = ldidx(eidx, (long long)N_EDGES + e, f64);
        float w = __ldg(ew + e);
        int pos = atomicAdd(&d_cur[tgt], 1);
        d_epack[pos] = ((unsigned long long)__float_as_uint(w) << 32) | (unsigned)(int)src;
    }
}

// ---------------- kernel 2d: F-space gather: msgF[n] = sum w*nf[src] ------
__global__ void k_gatherF(const float* __restrict__ nf) {
    int sub = threadIdx.x >> 3;
    int l = threadIdx.x & 7;
    int n = blockIdx.x * 32 + sub;
    int s = d_off[n], e = d_off[n + 1];

    float4 a0 = {0.f, 0.f, 0.f, 0.f};
    float4 a1 = {0.f, 0.f, 0.f, 0.f};
    float4 a2 = {0.f, 0.f, 0.f, 0.f};
    float4 a3 = {0.f, 0.f, 0.f, 0.f};
    int i = s;
    for (; i + 3 < e; i += 4) {
        unsigned long long p0 = d_epack[i];
        unsigned long long p1 = d_epack[i + 1];
        unsigned long long p2 = d_epack[i + 2];
        unsigned long long p3 = d_epack[i + 3];
        int s0 = (int)(unsigned)p0; float w0 = __uint_as_float((unsigned)(p0 >> 32));
        int s1 = (int)(unsigned)p1; float w1 = __uint_as_float((unsigned)(p1 >> 32));
        int s2 = (int)(unsigned)p2; float w2 = __uint_as_float((unsigned)(p2 >> 32));
        int s3 = (int)(unsigned)p3; float w3 = __uint_as_float((unsigned)(p3 >> 32));
        float4 v0 = *(const float4*)(nf + (size_t)s0 * F_DIM + l * 4);
        float4 v1 = *(const float4*)(nf + (size_t)s1 * F_DIM + l * 4);
        float4 v2 = *(const float4*)(nf + (size_t)s2 * F_DIM + l * 4);
        float4 v3 = *(const float4*)(nf + (size_t)s3 * F_DIM + l * 4);
        a0.x += v0.x * w0; a0.y += v0.y * w0; a0.z += v0.z * w0; a0.w += v0.w * w0;
        a1.x += v1.x * w1; a1.y += v1.y * w1; a1.z += v1.z * w1; a1.w += v1.w * w1;
        a2.x += v2.x * w2; a2.y += v2.y * w2; a2.z += v2.z * w2; a2.w += v2.w * w2;
        a3.x += v3.x * w3; a3.y += v3.y * w3; a3.z += v3.z * w3; a3.w += v3.w * w3;
    }
    for (; i < e; i++) {
        unsigned long long p0 = d_epack[i];
        int s0 = (int)(unsigned)p0; float w0 = __uint_as_float((unsigned)(p0 >> 32));
        float4 v0 = *(const float4*)(nf + (size_t)s0 * F_DIM + l * 4);
        a0.x += v0.x * w0; a0.y += v0.y * w0; a0.z += v0.z * w0; a0.w += v0.w * w0;
    }
    a0.x += a1.x + a2.x + a3.x;
    a0.y += a1.y + a2.y + a3.y;
    a0.z += a1.z + a2.z + a3.z;
    a0.w += a1.w + a2.w + a3.w;
    *(float4*)(d_msgF + (size_t)n * F_DIM + l * 4) = a0;
}

// ---------------- kernel 3: h = relu([nf,msgF]@B); pool into gsum ---------
// 128x128 block tile, 256 threads, 8x8 micro-tile, f32x2 FMA.
// 2D warp tiling (4 row-groups x 8 col-groups per warp) halves unique smem
// fragments per warp; B columns padded (col>>5)*4 for conflict-free banks.
#define BCOL(c) ((c) + (((c) >> 5) << 2))
__global__ __launch_bounds__(256, 2) void k_gemm_pool(const float* __restrict__ nf,
                                                      const void* __restrict__ batch) {
    __shared__ float As[16][132];   // [k][row]; stride 132 = 0 mod 4 -> float4-aligned rows
    __shared__ float Bs[16][140];   // [k][col padded]; 140 = 0 mod 4
    const int f64 = d_flag64;
    int t = threadIdx.x;
    int rowBase = blockIdx.x * 128;
    int w = t >> 5, lane = t & 31;
    int tc = (w & 1) * 8 + (lane & 7);        // 0..15 col-group (8 cols each)
    int tr = (w >> 1) * 4 + (lane >> 3);      // 0..15 row-group (8 rows each)

    unsigned long long acc[8][4];   // [row][col-pair] f32x2
    #pragma unroll
    for (int i = 0; i < 8; i++)
        #pragma unroll
        for (int j = 0; j < 4; j++) acc[i][j] = 0ULL;

    int ar_row = t >> 1, ar_half = t & 1;       // A loader mapping
    int bk = t >> 4, bc = (t & 15) * 8;         // B loader mapping
    int bcp = BCOL(bc);

    #pragma unroll
    for (int p = 0; p < 2; p++) {
        const float* Asrc = p ? d_msgF : nf;
        #pragma unroll
        for (int c = 0; c < 2; c++) {
            // A chunk: 128 rows x 16 k (transposed): thread loads 8 floats
            {
                const float4* ar = (const float4*)(Asrc + (size_t)(rowBase + ar_row) * F_DIM
                                                   + c * 16 + ar_half * 8);
                float4 v0 = ar[0], v1 = ar[1];
                int kb = ar_half * 8;
                As[kb + 0][ar_row] = v0.x; As[kb + 1][ar_row] = v0.y;
                As[kb + 2][ar_row] = v0.z; As[kb + 3][ar_row] = v0.w;
                As[kb + 4][ar_row] = v1.x; As[kb + 5][ar_row] = v1.y;
                As[kb + 6][ar_row] = v1.z; As[kb + 7][ar_row] = v1.w;
            }
            // B chunk: 16 k x 128 cols: thread loads 8 floats (padded layout)
            {
                const float4* wr = (const float4*)(d_B + (size_t)(p * 32 + c * 16 + bk) * H_DIM + bc);
                *(float4*)&Bs[bk][bcp]     = wr[0];
                *(float4*)&Bs[bk][bcp + 4] = wr[1];
            }
            __syncthreads();

            int c0p = BCOL(tc * 8);
            #pragma unroll
            for (int kk = 0; kk < 16; kk++) {
                float4 a0 = *(const float4*)&As[kk][tr * 8];
                float4 a1 = *(const float4*)&As[kk][tr * 8 + 4];
                float4 b0 = *(const float4*)&Bs[kk][c0p];
                float4 b1 = *(const float4*)&Bs[kk][c0p + 4];
                unsigned long long bp0 = pk2(b0.x, b0.y);
                unsigned long long bp1 = pk2(b0.z, b0.w);
                unsigned long long bp2 = pk2(b1.x, b1.y);
                unsigned long long bp3 = pk2(b1.z, b1.w);
                float av[8] = {a0.x, a0.y, a0.z, a0.w, a1.x, a1.y, a1.z, a1.w};
                #pragma unroll
                for (int i = 0; i < 8; i++) {
                    unsigned long long ap = pk2(av[i], av[i]);
                    fma2(acc[i][0], ap, bp0);
                    fma2(acc[i][1], ap, bp1);
                    fma2(acc[i][2], ap, bp2);
                    fma2(acc[i][3], ap, bp3);
                }
            }
            __syncthreads();
        }
    }

    // epilogue: relu + pool into per-graph sums
    int c0 = tc * 8;
    int r0 = rowBase + tr * 8;
    long long gidA = ldidx(batch, r0, f64);
    long long gidB = ldidx(batch, r0 + 7, f64);

    if (gidA == gidB) {   // sorted batch => all 8 rows same graph
        float s[8];
        #pragma unroll
        for (int j = 0; j < 8; j++) s[j] = 0.f;
        #pragma unroll
        for (int i = 0; i < 8; i++)
            #pragma unroll
            for (int j4 = 0; j4 < 4; j4++) {
                float lo, hi;
                upk2(lo, hi, acc[i][j4]);
                s[2 * j4]     += fmaxf(lo, 0.f);
                s[2 * j4 + 1] += fmaxf(hi, 0.f);
            }
        float* base = d_gsum + gidA * H_DIM + c0;
        red_add_v4(base,     s[0], s[1], s[2], s[3]);
        red_add_v4(base + 4, s[4], s[5], s[6], s[7]);
    } else {
        #pragma unroll
        for (int i = 0; i < 8; i++) {
            long long gid = ldidx(batch, r0 + i, f64);
            float v[8];
            #pragma unroll
            for (int j4 = 0; j4 < 4; j4++) {
                float lo, hi;
                upk2(lo, hi, acc[i][j4]);
                v[2 * j4]     = fmaxf(lo, 0.f);
                v[2 * j4 + 1] = fmaxf(hi, 0.f);
            }
            float* base = d_gsum + gid * H_DIM + c0;
            red_add_v4(base,     v[0], v[1], v[2], v[3]);
            red_add_v4(base + 4, v[4], v[5], v[6], v[7]);
        }
    }
}

// ---------------- kernel 4a: backbone + small heads, 8 graphs per block ---
__global__ void k_head_small8(const void* __restrict__ batch,
                              const float* __restrict__ W1, const float* __restrict__ W2,
                              const float* __restrict__ Wa, const float* __restrict__ Wact,
                              const float* __restrict__ Wv1, const float* __restrict__ Wv2,
                              float* __restrict__ out) {
    __shared__ float sg[8][128];
    __shared__ float s1s[8][128];
    __shared__ float ss[8][64];
    __shared__ float v1s[8][32];
    __shared__ float inv8[8];
    const int f64 = d_flag64;
    int gbase = blockIdx.x * 8, t = threadIdx.x;

    if (t < 8) {
        long long g = gbase + t;
        int lo = 0, hi = N_NODES;
        while (lo < hi) { int mid = (lo + hi) >> 1; if (ldidx(batch, mid, f64) < g) lo = mid + 1; else hi = mid; }
        int start = lo;
        hi = N_NODES;
        while (lo < hi) { int mid = (lo + hi) >> 1; if (ldidx(batch, mid, f64) < g + 1) lo = mid + 1; else hi = mid; }
        int cnt = lo - start;
        inv8[t] = (cnt > 0) ? 1.f / (float)cnt : 0.f;
    }
    __syncthreads();

    #pragma unroll
    for (int g8 = 0; g8 < 8; g8++)
        sg[g8][t] = d_gsum[(size_t)(gbase + g8) * H_DIM + t] * inv8[g8];
    __syncthreads();

    {
        float acc[8];
        #pragma unroll
        for (int g8 = 0; g8 < 8; g8++) acc[g8] = 0.f;
        #pragma unroll 4
        for (int k = 0; k < 128; k++) {
            float wv = __ldg(W1 + k * 128 + t) + __ldg(W1 + (k + 128) * 128 + t);
            #pragma unroll
            for (int g8 = 0; g8 < 8; g8++) acc[g8] += sg[g8][k] * wv;
        }
        #pragma unroll
        for (int g8 = 0; g8 < 8; g8++) s1s[g8][t] = fmaxf(acc[g8], 0.f);
    }
    __syncthreads();

    if (t < 64) {
        float acc[8];
        #pragma unroll
        for (int g8 = 0; g8 < 8; g8++) acc[g8] = 0.f;
        #pragma unroll 4
        for (int k = 0; k < 128; k++) {
            float wv = __ldg(W2 + k * 64 + t);
            #pragma unroll
            for (int g8 = 0; g8 < 8; g8++) acc[g8] += s1s[g8][k] * wv;
        }
        #pragma unroll
        for (int g8 = 0; g8 < 8; g8++) {
            float v = fmaxf(acc[g8], 0.f);
            ss[g8][t] = v;
            d_s2[(size_t)(gbase + g8) * 64 + t] = v;
        }
    }
    __syncthreads();

    if (t < 40) {
        int g8 = t / 5, j = t - g8 * 5;
        float acc = 0.f;
        #pragma unroll
        for (int k = 0; k < 64; k++) acc += ss[g8][k] * __ldg(Wa + k * 5 + j);
        out[OUT_A + (long long)(gbase + g8) * 5 + j] = acc;
    }
    if (t >= 64 && t < 96) {
        int idx = t - 64, g8 = idx >> 2, j = idx & 3;
        float acc = 0.f;
        #pragma unroll
        for (int k = 0; k < 64; k++) acc += ss[g8][k] * __ldg(Wact + k * 4 + j);
        out[OUT_ACT + (long long)(gbase + g8) * 4 + j] = acc;
    }
    {
        int g8 = t >> 4, jb = t & 15;
        #pragma unroll
        for (int rep = 0; rep < 2; rep++) {
            int j = jb + rep * 16;
            float acc = 0.f;
            #pragma unroll
            for (int k = 0; k < 64; k++) acc += ss[g8][k] * __ldg(Wv1 + k * 32 + j);
            v1s[g8][j] = fmaxf(acc, 0.f);
        }
    }
    __syncthreads();
    if (t < 8) {
        float acc = 0.f;
        #pragma unroll
        for (int k = 0; k < 32; k++) acc += v1s[t][k] * __ldg(Wv2 + k);
        out[OUT_V + gbase + t] = tanhf(acc);
    }
}

// ---------------- kernel 4b: big heads (source/target logits) -------------
__global__ void k_head_big(const float* __restrict__ Ws, const float* __restrict__ Wt,
                           float* __restrict__ out) {
    __shared__ float s2s[8][64];
    int gbase = blockIdx.x * 8;
    const float* W = blockIdx.y ? Wt : Ws;
    long long off = blockIdx.y ? OUT_T : OUT_S;
    int t = threadIdx.x;

    for (int i = t; i < 512; i += 128) s2s[i >> 6][i & 63] = d_s2[gbase * 64 + i];
    __syncthreads();

    for (int m = t; m < 1000; m += 128) {
        float acc[8];
        #pragma unroll
        for (int g8 = 0; g8 < 8; g8++) acc[g8] = 0.f;
        #pragma unroll 8
        for (int k = 0; k < 64; k++) {
            float wv = __ldg(W + k * 1000 + m);
            #pragma unroll
            for (int g8 = 0; g8 < 8; g8++) acc[g8] += s2s[g8][k] * wv;
        }
        #pragma unroll
        for (int g8 = 0; g8 < 8; g8++)
            out[off + (long long)(gbase + g8) * 1000 + m] = acc[g8];
    }
}

// ---------------- launch ---------------------------------------------------
extern "C" void kernel_launch(void* const* d_in, const int* in_sizes, int n_in,
                              void* d_out, int out_size) {
    const float* nf   = (const float*)d_in[0];
    const void*  eidx = d_in[1];
    const float* ew   = (const float*)d_in[2];
    // d_in[3] = layer_positions (unused)
    const void*  batch = d_in[4];
    int wb = n_in - 10;
    const float* Win  = (const float*)d_in[wb + 0];
    const float* Wmsg = (const float*)d_in[wb + 1];
    const float* W1   = (const float*)d_in[wb + 2];
    const float* W2   = (const float*)d_in[wb + 3];
    const float* Wa   = (const float*)d_in[wb + 4];
    const float* Ws   = (const float*)d_in[wb + 5];
    const float* Wt   = (const float*)d_in[wb + 6];
    const float* Wact = (const float*)d_in[wb + 7];
    const float* Wv1  = (const float*)d_in[wb + 8];
    const float* Wv2  = (const float*)d_in[wb + 9];
    float* out = (float*)d_out;

    k_setup<<<N_NODES / 256, 256>>>(eidx, Win, Wmsg);
    k_hist<<<N_EDGES / 1024, 256>>>(eidx);
    k_scan1<<<N_NODES / 256, 256>>>();
    k_scan2<<<1, 512>>>();
    k_scan3<<<N_NODES / 256, 256>>>();
    k_scatter<<<N_EDGES / 512, 256>>>(eidx, ew);
    k_gatherF<<<N_NODES / 32, 256>>>(nf);
    k_gemm_pool<<<N_NODES / 128, 256>>>(nf, batch);
    k_head_small8<<<G_NUM / 8, 128>>>(batch, W1, W2, Wa, Wact, Wv1, Wv2, out);
    k_head_big<<<dim3(64, 2), 128>>>(Ws, Wt, out);
}